// round 4
// baseline (speedup 1.0000x reference)
#include <cuda_runtime.h>

// Problem constants (from reference)
#define B        4096
#define N_ELEM   2048
#define N_NODES  1024
#define E2       4096
#define G        4                  // batches per block
#define NBLK     (B / G)            // 1024 blocks
#define THREADS  512

#define AXIAL_BYTES (G * N_ELEM * 4)          // 32 KB
#define CSR_BYTES   (E2 * 16)                 // 64 KB
#define SMEM_BYTES  (AXIAL_BYTES + CSR_BYTES) // 96 KB dynamic

// Scratch in __device__ globals (no allocation allowed).
__device__ int    g_csr_off[N_NODES + 1];
__device__ float4 g_csr[E2];       // {elem_as_float_bits, vx, vy, 0}
__device__ float  g_part[NBLK];
__device__ int    g_ctr = 0;

// ---------------------------------------------------------------------------
// Setup: deterministic CSR (edges grouped by node, sorted by original edge
// index within each node). One block, 1024 threads, shuffle-based scan.
// ---------------------------------------------------------------------------
__global__ __launch_bounds__(N_NODES)
void nel_setup_kernel(const int* __restrict__ node_ids,
                      const int* __restrict__ elem_ids,
                      const float* __restrict__ vecs) {
    __shared__ int s_beg[N_NODES];
    __shared__ int s_cur[N_NODES];
    __shared__ int s_idx[E2];
    __shared__ int s_wsum[32];
    const int tid  = threadIdx.x;
    const int lane = tid & 31;
    const int wrp  = tid >> 5;

    // 1. histogram
    s_beg[tid] = 0;
    __syncthreads();
    #pragma unroll
    for (int i = tid; i < E2; i += N_NODES)
        atomicAdd(&s_beg[node_ids[i]], 1);
    __syncthreads();

    // 2. exclusive scan via warp shuffles (3 barriers total)
    const int cnt = s_beg[tid];
    int v = cnt;
    #pragma unroll
    for (int o = 1; o < 32; o <<= 1) {
        int t = __shfl_up_sync(0xffffffffu, v, o);
        if (lane >= o) v += t;
    }
    if (lane == 31) s_wsum[wrp] = v;           // inclusive warp total
    __syncthreads();
    if (wrp == 0) {
        int w = s_wsum[lane];
        #pragma unroll
        for (int o = 1; o < 32; o <<= 1) {
            int t = __shfl_up_sync(0xffffffffu, w, o);
            if (lane >= o) w += t;
        }
        s_wsum[lane] = w - s_wsum[lane];        // exclusive warp prefix
    }
    __syncthreads();
    const int excl = v - cnt + s_wsum[wrp];
    s_beg[tid] = excl;
    s_cur[tid] = excl;
    __syncthreads();

    // 3. scatter edge indices into bins
    #pragma unroll
    for (int i = tid; i < E2; i += N_NODES) {
        int pos = atomicAdd(&s_cur[node_ids[i]], 1);
        s_idx[pos] = i;
    }
    __syncthreads();

    // 4. per-bin insertion sort -> deterministic order
    {
        const int beg = s_beg[tid], end = s_cur[tid];
        for (int a = beg + 1; a < end; a++) {
            int key = s_idx[a];
            int p = a - 1;
            while (p >= beg && s_idx[p] > key) { s_idx[p + 1] = s_idx[p]; p--; }
            s_idx[p + 1] = key;
        }
    }
    __syncthreads();

    // 5. write CSR (fused 16B records)
    g_csr_off[tid] = s_beg[tid];
    if (tid == 0) g_csr_off[N_NODES] = E2;
    #pragma unroll
    for (int i = tid; i < E2; i += N_NODES) {
        int idx = s_idx[i];
        float4 rec;
        rec.x = __int_as_float(elem_ids[idx]);
        rec.y = vecs[2 * idx];
        rec.z = vecs[2 * idx + 1];
        rec.w = 0.f;
        g_csr[i] = rec;
    }
}

// ---------------------------------------------------------------------------
// Main: one block = G=4 batch rows, 512 threads, 96KB dynamic smem.
// CSR records AND axial both staged in smem -> gather is pure LDS (29cyc)
// instead of dependent L2 LDG (250cyc). Last block finalizes.
// ---------------------------------------------------------------------------
__global__ __launch_bounds__(THREADS)
void nel_main_kernel(const float* __restrict__ EA,
                     const float* __restrict__ e,
                     const float* __restrict__ q,
                     const float* __restrict__ r,
                     float* __restrict__ out) {
    extern __shared__ unsigned char dyn_smem[];
    float*  s_axial = (float*)dyn_smem;                   // 32 KB, [elem][g]
    float4* s_csr   = (float4*)(dyn_smem + AXIAL_BYTES);  // 64 KB
    __shared__ float s_warp[THREADS / 32];
    __shared__ int   s_islast;

    const int tid = threadIdx.x;
    const int b0  = blockIdx.x * G;

    // --- stage CSR records (coalesced, independent loads: full MLP) ---
    #pragma unroll
    for (int i = tid; i < E2; i += THREADS)
        s_csr[i] = g_csr[i];

    // --- stage axial = EA*e, transposed: s_axial[elem*4 + g] ---
    {
        const int g  = tid & 3;
        const int c0 = tid >> 2;             // 0..127 (float4 column)
        const float4* EA4 = (const float4*)(EA + (size_t)(b0 + g) * N_ELEM);
        const float4* e4  = (const float4*)(e  + (size_t)(b0 + g) * N_ELEM);
        #pragma unroll
        for (int k = 0; k < (N_ELEM / 4) / (THREADS / 4); k++) {   // 4 iters
            int col = c0 + (THREADS / 4) * k;
            float4 a  = EA4[col];
            float4 ee = e4[col];
            int base = col * 16 + g;
            s_axial[base + 0]  = a.x * ee.x;
            s_axial[base + 4]  = a.y * ee.y;
            s_axial[base + 8]  = a.z * ee.z;
            s_axial[base + 12] = a.w * ee.w;
        }
    }
    __syncthreads();

    // --- gather per node (vectorized over the 4 batches), fuse loss ---
    const float4* sax4 = (const float4*)s_axial;
    float acc = 0.f;

    #pragma unroll
    for (int nn = 0; nn < N_NODES / THREADS; nn++) {    // 2 iters
        const int n   = tid + nn * THREADS;
        const int beg = g_csr_off[n];
        const int end = g_csr_off[n + 1];

        float4 ax = make_float4(0.f, 0.f, 0.f, 0.f);    // x-comp, g=0..3
        float4 ay = make_float4(0.f, 0.f, 0.f, 0.f);    // y-comp, g=0..3
        for (int p = beg; p < end; p++) {
            float4 rec = s_csr[p];                      // LDS.128
            int eid = __float_as_int(rec.x);
            float4 a = sax4[eid];                       // LDS.128
            ax.x += a.x * rec.y;  ax.y += a.y * rec.y;
            ax.z += a.z * rec.y;  ax.w += a.w * rec.y;
            ay.x += a.x * rec.z;  ay.y += a.y * rec.z;
            ay.z += a.z * rec.z;  ay.w += a.w * rec.z;
        }

        const float* axp = (const float*)&ax;
        const float* ayp = (const float*)&ay;
        #pragma unroll
        for (int g = 0; g < G; g++) {
            const float2* q2 = (const float2*)(q + (size_t)(b0 + g) * N_NODES * 2);
            const float2* r2 = (const float2*)(r + (size_t)(b0 + g) * N_NODES * 2);
            float2 qq = q2[n];
            float2 rr = r2[n];
            float dx = axp[g] - qq.x - rr.x;
            float dy = ayp[g] - qq.y - rr.y;
            acc += dx * dx + dy * dy;
        }
    }

    // --- block reduce ---
    #pragma unroll
    for (int o = 16; o > 0; o >>= 1)
        acc += __shfl_down_sync(0xffffffffu, acc, o);
    if ((tid & 31) == 0) s_warp[tid >> 5] = acc;
    __syncthreads();
    if (tid == 0) {
        float total = 0.f;
        #pragma unroll
        for (int w = 0; w < THREADS / 32; w++) total += s_warp[w];
        g_part[blockIdx.x] = total;
    }

    // --- last-block finalize (fixed-order double sum -> deterministic) ---
    __threadfence();
    if (tid == 0) {
        int old = atomicAdd(&g_ctr, 1);
        s_islast = (old == (int)gridDim.x - 1) ? 1 : 0;
    }
    __syncthreads();
    if (s_islast) {
        __threadfence();
        __shared__ double s_d[THREADS];
        double d = 0.0;
        #pragma unroll
        for (int i = tid; i < NBLK; i += THREADS) d += (double)g_part[i];
        s_d[tid] = d;
        __syncthreads();
        #pragma unroll
        for (int s = THREADS / 2; s > 0; s >>= 1) {
            if (tid < s) s_d[tid] += s_d[tid + s];
            __syncthreads();
        }
        if (tid == 0) {
            out[0] = (float)(s_d[0] / ((double)B * (double)N_NODES * 2.0));
            g_ctr = 0;   // reset for next graph replay
        }
    }
}

extern "C" void kernel_launch(void* const* d_in, const int* in_sizes, int n_in,
                              void* d_out, int out_size) {
    const float* EA       = (const float*)d_in[0];
    const float* e        = (const float*)d_in[1];
    const float* q        = (const float*)d_in[2];
    const float* r        = (const float*)d_in[3];
    const float* vecs     = (const float*)d_in[4];
    const int*   node_ids = (const int*)d_in[5];
    const int*   elem_ids = (const int*)d_in[6];
    float* out = (float*)d_out;

    // Opt into >48KB dynamic shared memory (idempotent; not a graph node).
    static int configured = 0;
    if (!configured) {
        cudaFuncSetAttribute(nel_main_kernel,
                             cudaFuncAttributeMaxDynamicSharedMemorySize,
                             SMEM_BYTES);
        configured = 1;
    }

    nel_setup_kernel<<<1, N_NODES>>>(node_ids, elem_ids, vecs);
    nel_main_kernel<<<NBLK, THREADS, SMEM_BYTES>>>(EA, e, q, r, out);
}

// round 5
// speedup vs baseline: 1.0363x; 1.0363x over previous
#include <cuda_runtime.h>

// Problem constants (from reference)
#define B        4096
#define N_ELEM   2048
#define N_NODES  1024
#define E2       4096
#define G        2                     // batches per group
#define NGROUPS  (B / G)               // 2048 groups
#define NBLK     296                   // 2 CTAs/SM x 148 SMs: one persistent wave
#define THREADS  512
#define NODES_PT (N_NODES / THREADS)   // 2 nodes per thread

// Scratch in __device__ globals (no allocation allowed).
__device__ int    g_off[N_NODES + 1];
__device__ int    g_elem[E2];
__device__ float2 g_vec[E2];
__device__ float  g_part[NBLK];
__device__ int    g_ctr = 0;

// Dynamic smem layout (bytes):
//  [0,      16K)   s_elem  : int[E2]
//  [16K,    48K)   s_vec   : float2[E2]
//  [48K,    52K+4) s_off   : int[N_NODES+1]
//  [56K,    72K)   s_axial : float2[N_ELEM]   (axial for the 2 batches)
//  [72K,   104K)   s_eae   : float[4*N_ELEM]  (EA_b0 | e_b0 | EA_b1 | e_b1)
#define OFF_ELEM   0
#define OFF_VEC    (16 * 1024)
#define OFF_OFF    (48 * 1024)
#define OFF_AXIAL  (56 * 1024)
#define OFF_EAE    (72 * 1024)
#define SMEM_BYTES (104 * 1024)

__device__ __forceinline__ unsigned smem_u32(const void* p) {
    return (unsigned)__cvta_generic_to_shared(p);
}
__device__ __forceinline__ void cp_async16(void* dst_smem, const void* src_gmem) {
    asm volatile("cp.async.ca.shared.global [%0], [%1], 16;\n"
                 :: "r"(smem_u32(dst_smem)), "l"(src_gmem) : "memory");
}
__device__ __forceinline__ void cp_commit() {
    asm volatile("cp.async.commit_group;\n" ::: "memory");
}
__device__ __forceinline__ void cp_wait_all() {
    asm volatile("cp.async.wait_group 0;\n" ::: "memory");
}

// ---------------------------------------------------------------------------
// Setup: deterministic CSR (edges grouped by node, sorted by original edge
// index within each node). One block, 1024 threads.
// ---------------------------------------------------------------------------
__global__ __launch_bounds__(N_NODES)
void nel_setup_kernel(const int* __restrict__ node_ids,
                      const int* __restrict__ elem_ids,
                      const float* __restrict__ vecs) {
    __shared__ int s_beg[N_NODES];
    __shared__ int s_cur[N_NODES];
    __shared__ int s_idx[E2];
    __shared__ int s_wsum[32];
    const int tid  = threadIdx.x;
    const int lane = tid & 31;
    const int wrp  = tid >> 5;

    // 1. histogram
    s_beg[tid] = 0;
    __syncthreads();
    #pragma unroll
    for (int i = tid; i < E2; i += N_NODES)
        atomicAdd(&s_beg[node_ids[i]], 1);
    __syncthreads();

    // 2. exclusive scan via warp shuffles
    const int cnt = s_beg[tid];
    int v = cnt;
    #pragma unroll
    for (int o = 1; o < 32; o <<= 1) {
        int t = __shfl_up_sync(0xffffffffu, v, o);
        if (lane >= o) v += t;
    }
    if (lane == 31) s_wsum[wrp] = v;
    __syncthreads();
    if (wrp == 0) {
        int w = s_wsum[lane];
        #pragma unroll
        for (int o = 1; o < 32; o <<= 1) {
            int t = __shfl_up_sync(0xffffffffu, w, o);
            if (lane >= o) w += t;
        }
        s_wsum[lane] = w - s_wsum[lane];
    }
    __syncthreads();
    const int excl = v - cnt + s_wsum[wrp];
    s_beg[tid] = excl;
    s_cur[tid] = excl;
    __syncthreads();

    // 3. scatter edge indices into bins
    #pragma unroll
    for (int i = tid; i < E2; i += N_NODES) {
        int pos = atomicAdd(&s_cur[node_ids[i]], 1);
        s_idx[pos] = i;
    }
    __syncthreads();

    // 4. per-bin insertion sort -> deterministic order
    {
        const int beg = s_beg[tid], end = s_cur[tid];
        for (int a = beg + 1; a < end; a++) {
            int key = s_idx[a];
            int p = a - 1;
            while (p >= beg && s_idx[p] > key) { s_idx[p + 1] = s_idx[p]; p--; }
            s_idx[p + 1] = key;
        }
    }
    __syncthreads();

    // 5. write split CSR arrays
    g_off[tid] = s_beg[tid];
    if (tid == 0) g_off[N_NODES] = E2;
    #pragma unroll
    for (int i = tid; i < E2; i += N_NODES) {
        int idx = s_idx[i];
        g_elem[i] = elem_ids[idx];
        g_vec[i]  = make_float2(vecs[2 * idx], vecs[2 * idx + 1]);
    }
}

// ---------------------------------------------------------------------------
// Main: persistent 296-block grid. Each block loops over batch-groups of G=2
// (strided by gridDim), with cp.async prefetch of the NEXT group's EA/e
// overlapping the CURRENT group's gather -> DRAM streams continuously.
// ---------------------------------------------------------------------------
__global__ __launch_bounds__(THREADS, 2)
void nel_main_kernel(const float* __restrict__ EA,
                     const float* __restrict__ e,
                     const float* __restrict__ q,
                     const float* __restrict__ r,
                     float* __restrict__ out) {
    extern __shared__ unsigned char dyn[];
    int*    s_elem  = (int*)   (dyn + OFF_ELEM);
    float2* s_vec   = (float2*)(dyn + OFF_VEC);
    int*    s_off   = (int*)   (dyn + OFF_OFF);
    float2* s_axial = (float2*)(dyn + OFF_AXIAL);
    float*  s_eae   = (float*) (dyn + OFF_EAE);
    __shared__ float s_warp[THREADS / 32];
    __shared__ int   s_islast;

    const int tid = threadIdx.x;

    // --- prologue: stage CSR (once) + first group's EA/e, all via cp.async ---
    int grp0 = blockIdx.x;                     // groups: grp0, grp0+NBLK, ...
    {
        #pragma unroll
        for (int i = tid; i < E2 / 4; i += THREADS)           // elem: 16KB
            cp_async16(&s_elem[i * 4], &g_elem[i * 4]);
        #pragma unroll
        for (int i = tid; i < E2 / 2; i += THREADS)           // vec: 32KB
            cp_async16(&s_vec[i * 2], &g_vec[i * 2]);
        #pragma unroll
        for (int i = tid; i < (N_NODES + 1 + 3) / 4; i += THREADS)
            cp_async16(&s_off[i * 4], &g_off[i * 4]);         // off: ~4KB
        if (grp0 < NGROUPS) {
            const float* srcEA = EA + (size_t)grp0 * G * N_ELEM;
            const float* srcE  = e  + (size_t)grp0 * G * N_ELEM;
            #pragma unroll
            for (int i = tid; i < (G * N_ELEM) / 4; i += THREADS) {
                cp_async16(&s_eae[i * 4],                srcEA + i * 4);
                cp_async16(&s_eae[G * N_ELEM + i * 4],   srcE  + i * 4);
            }
        }
        cp_commit();
    }

    float acc = 0.f;

    for (int grp = grp0; grp < NGROUPS; grp += NBLK) {
        // wait for this group's EA/e (and CSR on first iter); all threads sync
        cp_wait_all();
        __syncthreads();

        // --- build axial[elem] = {EA_b0*e_b0, EA_b1*e_b1} (smem->smem) ---
        // s_eae layout: [EA_b0 | EA_b1 | e_b0 | e_b1]? No: we loaded
        // [EA rows (b0,b1) contiguous 2*2048][e rows (b0,b1) contiguous].
        #pragma unroll
        for (int i = tid; i < N_ELEM; i += THREADS) {
            float a0 = s_eae[i]              * s_eae[2 * N_ELEM + i];
            float a1 = s_eae[N_ELEM + i]     * s_eae[3 * N_ELEM + i];
            s_axial[i] = make_float2(a0, a1);
        }
        __syncthreads();   // axial ready; s_eae now free for prefetch

        // --- prefetch NEXT group's EA/e while we gather this one ---
        int nxt = grp + NBLK;
        if (nxt < NGROUPS) {
            const float* srcEA = EA + (size_t)nxt * G * N_ELEM;
            const float* srcE  = e  + (size_t)nxt * G * N_ELEM;
            #pragma unroll
            for (int i = tid; i < (G * N_ELEM) / 4; i += THREADS) {
                cp_async16(&s_eae[i * 4],              srcEA + i * 4);
                cp_async16(&s_eae[G * N_ELEM + i * 4], srcE  + i * 4);
            }
        }
        cp_commit();

        // --- early-issue q,r loads (in flight during gather) ---
        const size_t qb = (size_t)grp * G * N_NODES * 2;
        const float2* q2 = (const float2*)(q + qb);
        const float2* r2 = (const float2*)(r + qb);
        float2 t00, t01, t10, t11;   // t[node][batch] = q + r
        {
            const int n0 = tid, n1 = tid + THREADS;
            float2 qa = q2[n0];            float2 ra = r2[n0];
            float2 qb_ = q2[N_NODES + n0]; float2 rb = r2[N_NODES + n0];
            float2 qc = q2[n1];            float2 rc = r2[n1];
            float2 qd = q2[N_NODES + n1];  float2 rd = r2[N_NODES + n1];
            t00 = make_float2(qa.x + ra.x, qa.y + ra.y);
            t01 = make_float2(qb_.x + rb.x, qb_.y + rb.y);
            t10 = make_float2(qc.x + rc.x, qc.y + rc.y);
            t11 = make_float2(qd.x + rd.x, qd.y + rd.y);
        }

        // --- gather + loss for the thread's 2 nodes ---
        #pragma unroll
        for (int nn = 0; nn < NODES_PT; nn++) {
            const int n   = tid + nn * THREADS;
            const int beg = s_off[n];
            const int end = s_off[n + 1];

            float ax0 = 0.f, ay0 = 0.f, ax1 = 0.f, ay1 = 0.f;
            for (int p = beg; p < end; p++) {
                int    eid = s_elem[p];
                float2 v   = s_vec[p];
                float2 a   = s_axial[eid];
                ax0 += a.x * v.x;  ay0 += a.x * v.y;
                ax1 += a.y * v.x;  ay1 += a.y * v.y;
            }
            float2 ta = (nn == 0) ? t00 : t10;   // batch b0
            float2 tb = (nn == 0) ? t01 : t11;   // batch b1
            float dx0 = ax0 - ta.x, dy0 = ay0 - ta.y;
            float dx1 = ax1 - tb.x, dy1 = ay1 - tb.y;
            acc += dx0 * dx0 + dy0 * dy0 + dx1 * dx1 + dy1 * dy1;
        }
        // loop top's wait+sync guards axial rebuild vs. this gather
        __syncthreads();
    }

    // --- block reduce (once) ---
    #pragma unroll
    for (int o = 16; o > 0; o >>= 1)
        acc += __shfl_down_sync(0xffffffffu, acc, o);
    if ((tid & 31) == 0) s_warp[tid >> 5] = acc;
    __syncthreads();
    if (tid == 0) {
        float total = 0.f;
        #pragma unroll
        for (int w = 0; w < THREADS / 32; w++) total += s_warp[w];
        g_part[blockIdx.x] = total;
    }

    // --- last-block finalize (fixed-order double sum -> deterministic) ---
    __threadfence();
    if (tid == 0) {
        int old = atomicAdd(&g_ctr, 1);
        s_islast = (old == (int)gridDim.x - 1) ? 1 : 0;
    }
    __syncthreads();
    if (s_islast) {
        __threadfence();
        __shared__ double s_d[THREADS];
        double d = 0.0;
        #pragma unroll
        for (int i = tid; i < NBLK; i += THREADS) d += (double)g_part[i];
        s_d[tid] = d;
        __syncthreads();
        #pragma unroll
        for (int s = THREADS / 2; s > 0; s >>= 1) {
            if (tid < s) s_d[tid] += s_d[tid + s];
            __syncthreads();
        }
        if (tid == 0) {
            out[0] = (float)(s_d[0] / ((double)B * (double)N_NODES * 2.0));
            g_ctr = 0;   // reset for next graph replay
        }
    }
}

extern "C" void kernel_launch(void* const* d_in, const int* in_sizes, int n_in,
                              void* d_out, int out_size) {
    const float* EA       = (const float*)d_in[0];
    const float* e        = (const float*)d_in[1];
    const float* q        = (const float*)d_in[2];
    const float* r        = (const float*)d_in[3];
    const float* vecs     = (const float*)d_in[4];
    const int*   node_ids = (const int*)d_in[5];
    const int*   elem_ids = (const int*)d_in[6];
    float* out = (float*)d_out;

    static int configured = 0;
    if (!configured) {
        cudaFuncSetAttribute(nel_main_kernel,
                             cudaFuncAttributeMaxDynamicSharedMemorySize,
                             SMEM_BYTES);
        configured = 1;
    }

    nel_setup_kernel<<<1, N_NODES>>>(node_ids, elem_ids, vecs);
    nel_main_kernel<<<NBLK, THREADS, SMEM_BYTES>>>(EA, e, q, r, out);
}

// round 6
// speedup vs baseline: 1.2502x; 1.2063x over previous
#include <cuda_runtime.h>

// Problem constants (from reference)
#define B        4096
#define N_ELEM   2048
#define N_NODES  1024
#define E2       4096
#define G        2                     // batches per group
#define NGROUPS  (B / G)               // 2048 groups
#define NBLK     152                   // 1 CTA/SM on GB300 (152 SMs), persistent
#define THREADS  512
#define NODES_PT (N_NODES / THREADS)   // 2 nodes per thread

// __device__ scratch (16B-aligned for cp.async.bulk sources).
__device__ __align__(16) int    g_elem[E2];
__device__ __align__(16) float2 g_vec[E2];
__device__ __align__(16) int    g_off[N_NODES + 4];   // padded to 16B multiple
__device__ float g_part[NBLK];
__device__ int   g_ctr = 0;

// Dynamic smem layout (bytes):
//  [0,    16K)  s_elem  : int[E2]
//  [16K,  48K)  s_vec   : float2[E2]
//  [48K,  53K)  s_off   : int[N_NODES+4] (4112B used)
//  [56K,  72K)  s_axial : float2[N_ELEM]
//  [72K, 136K)  buf0    : float[16384]  = [EA(2 rows)|e(2 rows)|q(grp)|r(grp)]
//  [136K,200K)  buf1
#define OFF_ELEM   0
#define OFF_VEC    (16 * 1024)
#define OFF_OFF    (48 * 1024)
#define OFF_AXIAL  (56 * 1024)
#define OFF_BUF0   (72 * 1024)
#define OFF_BUF1   (136 * 1024)
#define SMEM_BYTES (200 * 1024)

#define CSR_BYTES   (16384 + 32768 + 4112)   // elem + vec + off = 53264
#define GRP_BYTES   (4 * 16384)              // EA + e + q + r   = 65536

__device__ __forceinline__ unsigned smem_u32(const void* p) {
    return (unsigned)__cvta_generic_to_shared(p);
}
__device__ __forceinline__ void mbar_init(unsigned mbar, unsigned count) {
    asm volatile("mbarrier.init.shared.b64 [%0], %1;" :: "r"(mbar), "r"(count) : "memory");
}
__device__ __forceinline__ void mbar_expect_tx(unsigned mbar, unsigned bytes) {
    asm volatile("mbarrier.arrive.expect_tx.shared.b64 _, [%0], %1;"
                 :: "r"(mbar), "r"(bytes) : "memory");
}
__device__ __forceinline__ void mbar_wait(unsigned mbar, unsigned parity) {
    asm volatile(
        "{\n\t.reg .pred P;\n\t"
        "W%=:\n\t"
        "mbarrier.try_wait.parity.acquire.cta.shared::cta.b64 P, [%0], %1, 0x989680;\n\t"
        "@!P bra W%=;\n\t}"
        :: "r"(mbar), "r"(parity) : "memory");
}
__device__ __forceinline__ void bulk_g2s(unsigned dst_smem, const void* src,
                                         unsigned bytes, unsigned mbar) {
    asm volatile(
        "cp.async.bulk.shared::cta.global.mbarrier::complete_tx::bytes [%0], [%1], %2, [%3];"
        :: "r"(dst_smem), "l"(src), "r"(bytes), "r"(mbar) : "memory");
}

// ---------------------------------------------------------------------------
// Setup: deterministic CSR (edges grouped by node, sorted by original edge
// index within each node). One block, 1024 threads.
// ---------------------------------------------------------------------------
__global__ __launch_bounds__(N_NODES)
void nel_setup_kernel(const int* __restrict__ node_ids,
                      const int* __restrict__ elem_ids,
                      const float* __restrict__ vecs) {
    __shared__ int s_beg[N_NODES];
    __shared__ int s_cur[N_NODES];
    __shared__ int s_idx[E2];
    __shared__ int s_wsum[32];
    const int tid  = threadIdx.x;
    const int lane = tid & 31;
    const int wrp  = tid >> 5;

    // 1. histogram
    s_beg[tid] = 0;
    __syncthreads();
    #pragma unroll
    for (int i = tid; i < E2; i += N_NODES)
        atomicAdd(&s_beg[node_ids[i]], 1);
    __syncthreads();

    // 2. exclusive scan via warp shuffles
    const int cnt = s_beg[tid];
    int v = cnt;
    #pragma unroll
    for (int o = 1; o < 32; o <<= 1) {
        int t = __shfl_up_sync(0xffffffffu, v, o);
        if (lane >= o) v += t;
    }
    if (lane == 31) s_wsum[wrp] = v;
    __syncthreads();
    if (wrp == 0) {
        int w = s_wsum[lane];
        #pragma unroll
        for (int o = 1; o < 32; o <<= 1) {
            int t = __shfl_up_sync(0xffffffffu, w, o);
            if (lane >= o) w += t;
        }
        s_wsum[lane] = w - s_wsum[lane];
    }
    __syncthreads();
    const int excl = v - cnt + s_wsum[wrp];
    s_beg[tid] = excl;
    s_cur[tid] = excl;
    __syncthreads();

    // 3. scatter edge indices into bins
    #pragma unroll
    for (int i = tid; i < E2; i += N_NODES) {
        int pos = atomicAdd(&s_cur[node_ids[i]], 1);
        s_idx[pos] = i;
    }
    __syncthreads();

    // 4. per-bin insertion sort -> deterministic order
    {
        const int beg = s_beg[tid], end = s_cur[tid];
        for (int a = beg + 1; a < end; a++) {
            int key = s_idx[a];
            int p = a - 1;
            while (p >= beg && s_idx[p] > key) { s_idx[p + 1] = s_idx[p]; p--; }
            s_idx[p + 1] = key;
        }
    }
    __syncthreads();

    // 5. write split CSR arrays
    g_off[tid] = s_beg[tid];
    if (tid == 0) {
        g_off[N_NODES]     = E2;
        g_off[N_NODES + 1] = E2;
        g_off[N_NODES + 2] = E2;
        g_off[N_NODES + 3] = E2;
    }
    #pragma unroll
    for (int i = tid; i < E2; i += N_NODES) {
        int idx = s_idx[i];
        g_elem[i] = elem_ids[idx];
        g_vec[i]  = make_float2(vecs[2 * idx], vecs[2 * idx + 1]);
    }
}

// ---------------------------------------------------------------------------
// Main: 152 persistent blocks, 1/SM. ALL bulk data (EA/e/q/r per group and the
// CSR once) moves via cp.async.bulk (TMA path) -> near-zero LSU issue cost for
// the 128MB compulsory stream. Double-buffered groups, mbarrier completion.
// ---------------------------------------------------------------------------
__global__ __launch_bounds__(THREADS, 1)
void nel_main_kernel(const float* __restrict__ EA,
                     const float* __restrict__ e,
                     const float* __restrict__ q,
                     const float* __restrict__ r,
                     float* __restrict__ out) {
    extern __shared__ unsigned char dyn[];
    int*    s_elem  = (int*)   (dyn + OFF_ELEM);
    float2* s_vec   = (float2*)(dyn + OFF_VEC);
    int*    s_off   = (int*)   (dyn + OFF_OFF);
    float2* s_axial = (float2*)(dyn + OFF_AXIAL);
    float*  s_buf0  = (float*) (dyn + OFF_BUF0);
    float*  s_buf1  = (float*) (dyn + OFF_BUF1);
    __shared__ __align__(8) unsigned long long s_mbar[2];
    __shared__ float s_warp[THREADS / 32];
    __shared__ int   s_islast;

    const int tid = threadIdx.x;
    const int g0  = blockIdx.x;
    const int cnt = (NGROUPS - g0 + NBLK - 1) / NBLK;   // groups for this block
    const unsigned mb0 = smem_u32(&s_mbar[0]);
    const unsigned mb1 = smem_u32(&s_mbar[1]);

    if (tid == 0) { mbar_init(mb0, 1); mbar_init(mb1, 1); }
    __syncthreads();

    // --- prologue: CSR + group k=0 on mb0, group k=1 on mb1 ---
    if (tid == 0) {
        {
            int grp = g0;
            const float* bEA = EA + (size_t)grp * G * N_ELEM;
            const float* be  = e  + (size_t)grp * G * N_ELEM;
            const float* bq  = q  + (size_t)grp * G * N_NODES * 2;
            const float* br  = r  + (size_t)grp * G * N_NODES * 2;
            mbar_expect_tx(mb0, CSR_BYTES + GRP_BYTES);
            bulk_g2s(smem_u32(s_elem), g_elem, 16384, mb0);
            bulk_g2s(smem_u32(s_vec),  g_vec,  32768, mb0);
            bulk_g2s(smem_u32(s_off),  g_off,  4112,  mb0);
            bulk_g2s(smem_u32(s_buf0),         bEA, 16384, mb0);
            bulk_g2s(smem_u32(s_buf0 + 4096),  be,  16384, mb0);
            bulk_g2s(smem_u32(s_buf0 + 8192),  bq,  16384, mb0);
            bulk_g2s(smem_u32(s_buf0 + 12288), br,  16384, mb0);
        }
        if (cnt > 1) {
            int grp = g0 + NBLK;
            const float* bEA = EA + (size_t)grp * G * N_ELEM;
            const float* be  = e  + (size_t)grp * G * N_ELEM;
            const float* bq  = q  + (size_t)grp * G * N_NODES * 2;
            const float* br  = r  + (size_t)grp * G * N_NODES * 2;
            mbar_expect_tx(mb1, GRP_BYTES);
            bulk_g2s(smem_u32(s_buf1),         bEA, 16384, mb1);
            bulk_g2s(smem_u32(s_buf1 + 4096),  be,  16384, mb1);
            bulk_g2s(smem_u32(s_buf1 + 8192),  bq,  16384, mb1);
            bulk_g2s(smem_u32(s_buf1 + 12288), br,  16384, mb1);
        }
    }

    float acc = 0.f;
    unsigned ph0 = 0, ph1 = 0;

    for (int k = 0; k < cnt; k++) {
        const int bsel = k & 1;
        float* buf = bsel ? s_buf1 : s_buf0;
        const unsigned mb = bsel ? mb1 : mb0;

        // wait for this buffer's data
        if (bsel) { mbar_wait(mb, ph1); ph1 ^= 1; }
        else      { mbar_wait(mb, ph0); ph0 ^= 1; }

        // --- build axial[elem] = {EA_b0*e_b0, EA_b1*e_b1} ---
        #pragma unroll
        for (int i = tid; i < N_ELEM; i += THREADS) {
            float a0 = buf[i]          * buf[4096 + i];
            float a1 = buf[N_ELEM + i] * buf[4096 + N_ELEM + i];
            s_axial[i] = make_float2(a0, a1);
        }
        __syncthreads();

        // --- gather + loss for this thread's 2 nodes, both batches ---
        const float2* sq = (const float2*)(buf + 8192);
        const float2* sr = (const float2*)(buf + 12288);
        #pragma unroll
        for (int nn = 0; nn < NODES_PT; nn++) {
            const int n   = tid + nn * THREADS;
            const int beg = s_off[n];
            const int end = s_off[n + 1];

            float ax0 = 0.f, ay0 = 0.f, ax1 = 0.f, ay1 = 0.f;
            for (int p = beg; p < end; p++) {
                int    eid = s_elem[p];
                float2 v   = s_vec[p];
                float2 a   = s_axial[eid];
                ax0 += a.x * v.x;  ay0 += a.x * v.y;
                ax1 += a.y * v.x;  ay1 += a.y * v.y;
            }
            float2 qq0 = sq[n];            float2 rr0 = sr[n];
            float2 qq1 = sq[N_NODES + n];  float2 rr1 = sr[N_NODES + n];
            float dx0 = ax0 - qq0.x - rr0.x, dy0 = ay0 - qq0.y - rr0.y;
            float dx1 = ax1 - qq1.x - rr1.x, dy1 = ay1 - qq1.y - rr1.y;
            acc += dx0 * dx0 + dy0 * dy0 + dx1 * dx1 + dy1 * dy1;
        }
        __syncthreads();   // all threads done reading buf before refill

        // --- prefetch group k+2 into this buffer ---
        if (tid == 0 && k + 2 < cnt) {
            int grp = g0 + (k + 2) * NBLK;
            const float* bEA = EA + (size_t)grp * G * N_ELEM;
            const float* be  = e  + (size_t)grp * G * N_ELEM;
            const float* bq  = q  + (size_t)grp * G * N_NODES * 2;
            const float* br  = r  + (size_t)grp * G * N_NODES * 2;
            mbar_expect_tx(mb, GRP_BYTES);
            bulk_g2s(smem_u32(buf),         bEA, 16384, mb);
            bulk_g2s(smem_u32(buf + 4096),  be,  16384, mb);
            bulk_g2s(smem_u32(buf + 8192),  bq,  16384, mb);
            bulk_g2s(smem_u32(buf + 12288), br,  16384, mb);
        }
    }

    // --- block reduce ---
    #pragma unroll
    for (int o = 16; o > 0; o >>= 1)
        acc += __shfl_down_sync(0xffffffffu, acc, o);
    if ((tid & 31) == 0) s_warp[tid >> 5] = acc;
    __syncthreads();
    if (tid == 0) {
        float total = 0.f;
        #pragma unroll
        for (int w = 0; w < THREADS / 32; w++) total += s_warp[w];
        g_part[blockIdx.x] = total;
    }

    // --- last-block finalize (fixed-order double sum -> deterministic) ---
    __threadfence();
    if (tid == 0) {
        int old = atomicAdd(&g_ctr, 1);
        s_islast = (old == (int)gridDim.x - 1) ? 1 : 0;
    }
    __syncthreads();
    if (s_islast) {
        __threadfence();
        __shared__ double s_d[THREADS];
        double d = 0.0;
        #pragma unroll
        for (int i = tid; i < NBLK; i += THREADS) d += (double)g_part[i];
        s_d[tid] = d;
        __syncthreads();
        #pragma unroll
        for (int s = THREADS / 2; s > 0; s >>= 1) {
            if (tid < s) s_d[tid] += s_d[tid + s];
            __syncthreads();
        }
        if (tid == 0) {
            out[0] = (float)(s_d[0] / ((double)B * (double)N_NODES * 2.0));
            g_ctr = 0;   // reset for next graph replay
        }
    }
}

extern "C" void kernel_launch(void* const* d_in, const int* in_sizes, int n_in,
                              void* d_out, int out_size) {
    const float* EA       = (const float*)d_in[0];
    const float* e        = (const float*)d_in[1];
    const float* q        = (const float*)d_in[2];
    const float* r        = (const float*)d_in[3];
    const float* vecs     = (const float*)d_in[4];
    const int*   node_ids = (const int*)d_in[5];
    const int*   elem_ids = (const int*)d_in[6];
    float* out = (float*)d_out;

    static int configured = 0;
    if (!configured) {
        cudaFuncSetAttribute(nel_main_kernel,
                             cudaFuncAttributeMaxDynamicSharedMemorySize,
                             SMEM_BYTES);
        configured = 1;
    }

    nel_setup_kernel<<<1, N_NODES>>>(node_ids, elem_ids, vecs);
    nel_main_kernel<<<NBLK, THREADS, SMEM_BYTES>>>(EA, e, q, r, out);
}